// round 1
// baseline (speedup 1.0000x reference)
#include <cuda_runtime.h>
#include <cuda_bf16.h>
#include <cstdint>
#include <cstdio>

// Problem constants
#define BB   32
#define SS   4096
#define VV   128
#define NSEG 2050            // S/2 + 2
#define OUTMAIN (BB * SS * 2 * VV)   // 33,554,432 floats
#define TS   128             // tokens per main-kernel block

// ---------------- device scratch (static globals; no allocation) -------------
__device__ float d_pe[SS * VV];                 // sinusoidal PE table
__device__ float d_G[BB * VV * VV];             // per-batch Gram matrix
__device__ float d_sx[BB * VV];                 // per-batch column sums of xseq
__device__ int   d_segid[BB * SS];              // inclusive cumsum of rising edges
__device__ int   d_nedges[BB];
__device__ float d_segsum[(size_t)BB * NSEG * VV];
__device__ int   d_segcnt[BB * NSEG];
__device__ float d_attnseg[(size_t)BB * NSEG * VV];
__device__ float d_A[VV * VV];                  // Wq^T Wk / 64
__device__ float d_WvT[VV * VV];                // Wv transposed
__device__ float d_w1[VV];                      // bq^T Wk / 64
__device__ float d_qb[VV];                      // Wq^T bk
__device__ float d_bqbk;                        // bq . bk
__device__ float d_alpha[BB * VV];              // (Wq^T p + S Wq^T bk)/64
__device__ float d_r[BB * VV];                  // Wv sx
__device__ float d_cextra[BB * VV];
__device__ float d_H[BB * VV * VV];             // G @ Wv^T
__device__ float d_M[BB * VV * VV];             // attn matrix per batch
__device__ float d_c[BB * VV];                  // attn bias per batch

// packed f32x2 FMA (Blackwell)
__device__ __forceinline__ void ffma2(float2& d, float2 a, float2 b) {
    asm("fma.rn.f32x2 %0, %1, %2, %0;"
        : "+l"(reinterpret_cast<unsigned long long&>(d))
        : "l"(reinterpret_cast<unsigned long long&>(a)),
          "l"(reinterpret_cast<unsigned long long&>(b)));
}

// ---------------- 0) zero accumulators ---------------------------------------
__global__ void k_zero() {
    size_t i0 = (size_t)blockIdx.x * blockDim.x + threadIdx.x;
    size_t stride = (size_t)gridDim.x * blockDim.x;
    for (size_t i = i0; i < (size_t)BB * VV * VV; i += stride) d_G[i] = 0.f;
    for (size_t i = i0; i < (size_t)BB * VV; i += stride)      d_sx[i] = 0.f;
    for (size_t i = i0; i < (size_t)BB * NSEG * VV; i += stride) d_segsum[i] = 0.f;
    for (size_t i = i0; i < (size_t)BB * NSEG; i += stride)    d_segcnt[i] = 0;
}

// ---------------- 1) PE table -------------------------------------------------
__global__ void k_pe() {
    int gid = blockIdx.x * blockDim.x + threadIdx.x;   // S*64 threads total
    int t = gid >> 6, i = gid & 63;
    const float kScale = -0.07195578472185053f;        // -(ln 10000)/128 as f32
    float div = expf((float)(2 * i) * kScale);
    float s, c;
    sincosf((float)t * div, &s, &c);
    d_pe[t * VV + 2 * i]     = s;
    d_pe[t * VV + 2 * i + 1] = c;
}

// ---------------- 2) rising-edge scan per batch -------------------------------
__global__ void k_scan(const float* __restrict__ sp, float* __restrict__ out, int tail) {
    int b = blockIdx.x, tid = threadIdx.x;
    int base = tid * 16;
    const float* row = sp + (size_t)b * SS;
    float prev = (base == 0) ? -1.0f : row[base - 1];
    int loc[16]; int run = 0;
#pragma unroll
    for (int e = 0; e < 16; e++) {
        float cur = row[base + e];
        int mk = (cur >= 0.5f) && !(prev >= 0.5f);
        run += mk; loc[e] = run; prev = cur;
    }
    __shared__ int ss[256];
    ss[tid] = run; __syncthreads();
    int val = run;
    for (int o = 1; o < 256; o <<= 1) {
        int add = (tid >= o) ? ss[tid - o] : 0;
        __syncthreads();
        val += add; ss[tid] = val;
        __syncthreads();
    }
    int excl = val - run;
#pragma unroll
    for (int e = 0; e < 16; e++) d_segid[b * SS + base + e] = excl + loc[e];
    if (tid == 255) {
        d_nedges[b] = val;
        if (b < tail) out[(size_t)OUTMAIN + b] = (float)(val + 1);  // num_time_seq
    }
    if (b == 0) {
        for (int idx = BB + tid; idx < tail; idx += 256) out[(size_t)OUTMAIN + idx] = 0.f;
    }
}

// ---------------- 3) batch-independent precompute ------------------------------
__global__ void k_p0(const float* __restrict__ Wq, const float* __restrict__ bq,
                     const float* __restrict__ Wk, const float* __restrict__ bk,
                     const float* __restrict__ Wv) {
    int a = blockIdx.x, tid = threadIdx.x;
    __shared__ float wq[VV];
    wq[tid] = Wq[tid * VV + a];
    __syncthreads();
    float acc = 0.f;
    for (int i = 0; i < VV; i++) acc += wq[i] * Wk[i * VV + tid];
    d_A[a * VV + tid] = acc * (1.f / 64.f);
    d_WvT[a * VV + tid] = Wv[tid * VV + a];
    if (tid == 0) {
        float s = 0.f, w = 0.f;
        for (int i = 0; i < VV; i++) { s += wq[i] * bk[i]; w += bq[i] * Wk[i * VV + a]; }
        d_qb[a] = s;
        d_w1[a] = w * (1.f / 64.f);
        if (a == 0) {
            float z = 0.f;
            for (int i = 0; i < VV; i++) z += bq[i] * bk[i];
            d_bqbk = z;
        }
    }
}

// ---------------- 4) main: x1 write + Gram(upper) + sx + segment sums ----------
__global__ void __launch_bounds__(256, 2)
k_main(const float* __restrict__ bert, float* __restrict__ out) {
    extern __shared__ float sm[];
    float* xs  = sm;                       // TS * VV floats
    int*   sgid = (int*)(sm + TS * VV);    // TS ints
    int b = blockIdx.y, t0 = blockIdx.x * TS, tid = threadIdx.x;
    const float* bp = bert + ((size_t)b * SS + t0) * VV;
    float* ox = out + ((size_t)b * SS + t0) * (2 * VV) + VV;

    for (int idx = tid; idx < TS * VV; idx += 256) {
        int t = idx >> 7, v = idx & 127;
        float pe = d_pe[(t0 + t) * VV + v];
        float x  = bp[idx];
        ox[t * 2 * VV + v] = x + pe;       // x1 half of output
        xs[idx] = x + 2.f * pe;            // xseq
    }
    for (int i = tid; i < TS; i += 256) sgid[i] = d_segid[b * SS + t0 + i];
    __syncthreads();

    // Gram phase: 136 upper-triangle 8x8 tiles of the 128x128 Gram matrix
    if (tid < 136) {
        int rem = tid, ti = 0;
        while (rem >= 16 - ti) { rem -= 16 - ti; ti++; }
        int tj = ti + rem;
        int a0 = ti * 8, c0 = tj * 8;
        float2 acc2[8][4];
#pragma unroll
        for (int p = 0; p < 8; p++)
#pragma unroll
            for (int q = 0; q < 4; q++) acc2[p][q] = make_float2(0.f, 0.f);

        for (int t = 0; t < TS; t++) {
            const float4 A0 = *(const float4*)&xs[t * VV + a0];
            const float4 A1 = *(const float4*)&xs[t * VV + a0 + 4];
            const float4 C0 = *(const float4*)&xs[t * VV + c0];
            const float4 C1 = *(const float4*)&xs[t * VV + c0 + 4];
            float av[8] = {A0.x, A0.y, A0.z, A0.w, A1.x, A1.y, A1.z, A1.w};
            float2 cp[4] = {make_float2(C0.x, C0.y), make_float2(C0.z, C0.w),
                            make_float2(C1.x, C1.y), make_float2(C1.z, C1.w)};
#pragma unroll
            for (int p = 0; p < 8; p++) {
                float2 ap = make_float2(av[p], av[p]);
#pragma unroll
                for (int q = 0; q < 4; q++) ffma2(acc2[p][q], ap, cp[q]);
            }
        }
        float* Gb = d_G + (size_t)b * VV * VV;
#pragma unroll
        for (int p = 0; p < 8; p++)
#pragma unroll
            for (int q = 0; q < 4; q++) {
                atomicAdd(&Gb[(a0 + p) * VV + c0 + 2 * q],     acc2[p][q].x);
                atomicAdd(&Gb[(a0 + p) * VV + c0 + 2 * q + 1], acc2[p][q].y);
            }
    }

    // segment-sum phase: 2 halves x 128 columns; run-length accumulate, flush on edge
    {
        int half = tid >> 7, v = tid & 127;
        int tsrt = half * (TS / 2), tend = tsrt + TS / 2;
        float acc = 0.f, tot = 0.f;
        int cur = sgid[tsrt], cnt = 0;
        for (int t = tsrt; t < tend; t++) {
            int s = sgid[t];
            if (s != cur) {
                atomicAdd(&d_segsum[((size_t)b * NSEG + cur) * VV + v], acc);
                if (v == 0) atomicAdd(&d_segcnt[b * NSEG + cur], cnt);
                acc = 0.f; cnt = 0; cur = s;
            }
            float x = xs[t * VV + v];
            acc += x; tot += x; cnt++;
        }
        atomicAdd(&d_segsum[((size_t)b * NSEG + cur) * VV + v], acc);
        if (v == 0) atomicAdd(&d_segcnt[b * NSEG + cur], cnt);
        atomicAdd(&d_sx[b * VV + v], tot);
    }
}

// ---------------- 5) symmetrize G ----------------------------------------------
__global__ void k_sym() {
    int b = blockIdx.x;
    float* Gb = d_G + (size_t)b * VV * VV;
    for (int idx = threadIdx.x; idx < VV * VV; idx += blockDim.x) {
        int a = idx >> 7, c = idx & 127;
        if (a < c) Gb[c * VV + a] = Gb[a * VV + c];
    }
}

// ---------------- 6) per-batch small vectors ------------------------------------
__global__ void k_vec(const float* __restrict__ Wq, const float* __restrict__ bq,
                      const float* __restrict__ Wk, const float* __restrict__ Wv,
                      const float* __restrict__ bv) {
    int b = blockIdx.x, tid = threadIdx.x;
    __shared__ float sxs[VV], ps[VV], rs[VV], red[VV];
    sxs[tid] = d_sx[b * VV + tid];
    __syncthreads();
    float p = 0.f, r = 0.f;
    for (int e = 0; e < VV; e++) {
        p += Wk[tid * VV + e] * sxs[e];
        r += Wv[tid * VV + e] * sxs[e];
    }
    ps[tid] = p; rs[tid] = r;
    d_r[b * VV + tid] = r;
    __syncthreads();
    float qp = 0.f;
    for (int i = 0; i < VV; i++) qp += Wq[i * VV + tid] * ps[i];
    d_alpha[b * VV + tid] = (qp + (float)SS * d_qb[tid]) * (1.f / 64.f);
    red[tid] = bq[tid] * ps[tid];
    __syncthreads();
    for (int o = 64; o > 0; o >>= 1) {
        if (tid < o) red[tid] += red[tid + o];
        __syncthreads();
    }
    float bqp = red[0];
    d_cextra[b * VV + tid] =
        (bqp * bv[tid] + d_bqbk * (rs[tid] + (float)SS * bv[tid])) * (1.f / 64.f);
}

// ---------------- 7) H = G @ Wv^T (batched) --------------------------------------
__global__ void k_h() {
    int b = blockIdx.y, e0 = blockIdx.x * 16, tid = threadIdx.x;
    __shared__ float Gs[16 * VV];
    const float* Gb = d_G + (size_t)b * VV * VV;
#pragma unroll
    for (int r = 0; r < 16; r++) Gs[r * VV + tid] = Gb[(e0 + r) * VV + tid];
    __syncthreads();
    float acc[16];
#pragma unroll
    for (int e = 0; e < 16; e++) acc[e] = 0.f;
    for (int c = 0; c < VV; c++) {
        float w = d_WvT[c * VV + tid];
#pragma unroll
        for (int e = 0; e < 16; e++) acc[e] += Gs[e * VV + c] * w;
    }
    float* Hb = d_H + (size_t)b * VV * VV;
#pragma unroll
    for (int e = 0; e < 16; e++) Hb[(e0 + e) * VV + tid] = acc[e];
}

// ---------------- 8) M = A @ H + rank1, c = w1 @ H + cextra -----------------------
__global__ void k_m(const float* __restrict__ bv) {
    int b = blockIdx.y, rg = blockIdx.x, a0 = rg * 16, tid = threadIdx.x;
    __shared__ float As[16 * VV], w1s[VV];
#pragma unroll
    for (int r = 0; r < 16; r++) As[r * VV + tid] = d_A[(a0 + r) * VV + tid];
    w1s[tid] = d_w1[tid];
    __syncthreads();
    float acc[16]; float cacc = 0.f;
#pragma unroll
    for (int a = 0; a < 16; a++) acc[a] = 0.f;
    const float* Hb = d_H + (size_t)b * VV * VV;
    for (int e = 0; e < VV; e++) {
        float h = Hb[e * VV + tid];
#pragma unroll
        for (int a = 0; a < 16; a++) acc[a] += As[a * VV + e] * h;
        if (rg == 0) cacc += w1s[e] * h;
    }
    float bvj = bv[tid];
    float rj  = d_r[b * VV + tid];
    float* Mb = d_M + (size_t)b * VV * VV;
#pragma unroll
    for (int a = 0; a < 16; a++)
        Mb[(a0 + a) * VV + tid] = acc[a] + d_alpha[b * VV + a0 + a] * bvj
                                + (d_qb[a0 + a] * (1.f / 64.f)) * rj;
    if (rg == 0) d_c[b * VV + tid] = cacc + d_cextra[b * VV + tid];
}

// ---------------- 9) attn per segment: attnseg = mean @ M + c --------------------
__global__ void k_attnseg() {
    int b = blockIdx.y, g0 = blockIdx.x * 16, tid = threadIdx.x;
    int ne = d_nedges[b];
    if (g0 > ne) return;
    int ng = min(16, ne + 1 - g0);
    __shared__ float mean[16 * VV];
#pragma unroll
    for (int r = 0; r < 16; r++) {
        float val = 0.f;
        if (r < ng) {
            int cnt = d_segcnt[b * NSEG + g0 + r];
            float den = fmaxf((float)cnt, 1.f);
            val = d_segsum[((size_t)b * NSEG + g0 + r) * VV + tid] / den;
        }
        mean[r * VV + tid] = val;
    }
    __syncthreads();
    float cj = d_c[b * VV + tid];
    float acc[16];
#pragma unroll
    for (int s = 0; s < 16; s++) acc[s] = cj;
    const float* Mb = d_M + (size_t)b * VV * VV;
    for (int v = 0; v < VV; v++) {
        float m = Mb[v * VV + tid];
#pragma unroll
        for (int s = 0; s < 16; s++) acc[s] += mean[s * VV + v] * m;
    }
    for (int s = 0; s < ng; s++)
        d_attnseg[((size_t)b * NSEG + g0 + s) * VV + tid] = acc[s];
}

// ---------------- 10) broadcast segment attention to tokens ----------------------
__global__ void k_out(float* __restrict__ out) {
    int b = blockIdx.y, t0 = blockIdx.x * 32, tid = threadIdx.x;
    __shared__ int sg[32];
    if (tid < 32) sg[tid] = d_segid[b * SS + t0 + tid];
    __syncthreads();
    for (int idx = tid; idx < 32 * VV; idx += 256) {
        int t = idx >> 7, v = idx & 127;
        int g = sg[t];
        out[((size_t)b * SS + t0 + t) * (2 * VV) + v] =
            d_attnseg[((size_t)b * NSEG + g) * VV + v];
    }
}

// ---------------- launch -----------------------------------------------------------
extern "C" void kernel_launch(void* const* d_in, const int* in_sizes, int n_in,
                              void* d_out, int out_size) {
    const float* bert = (const float*)d_in[0];
    const float* sp   = (const float*)d_in[1];
    const float* Wq   = (const float*)d_in[2];
    const float* bq   = (const float*)d_in[3];
    const float* Wk   = (const float*)d_in[4];
    const float* bk   = (const float*)d_in[5];
    const float* Wv   = (const float*)d_in[6];
    const float* bv   = (const float*)d_in[7];
    float* out = (float*)d_out;
    int tail = out_size - OUTMAIN;
    if (tail < 0) tail = 0;

    const int smem_main = TS * VV * sizeof(float) + TS * sizeof(int);
    cudaFuncSetAttribute(k_main, cudaFuncAttributeMaxDynamicSharedMemorySize, smem_main);

    k_zero<<<1024, 256>>>();
    k_pe<<<(SS * 64) / 128, 128>>>();
    k_scan<<<BB, 256>>>(sp, out, tail);
    k_p0<<<VV, VV>>>(Wq, bq, Wk, bk, Wv);
    k_main<<<dim3(SS / TS, BB), 256, smem_main>>>(bert, out);
    k_sym<<<BB, 256>>>();
    k_vec<<<BB, VV>>>(Wq, bq, Wk, Wv, bv);
    k_h<<<dim3(8, BB), VV>>>();
    k_m<<<dim3(8, BB), VV>>>(bv);
    k_attnseg<<<dim3((NSEG + 15) / 16, BB), VV>>>();
    k_out<<<dim3(SS / 32, BB), 256>>>(out);
}

// round 2
// speedup vs baseline: 1.2947x; 1.2947x over previous
#include <cuda_runtime.h>
#include <cuda_bf16.h>
#include <cstdint>

#define BB   32
#define SS   4096
#define VV   128
#define NSEG 2050
#define OUTMAIN (BB * SS * 2 * VV)
#define TS   128

// ---------------- device scratch ----------------
__device__ float d_pe[SS * VV];
__device__ float d_G[BB * VV * VV];
__device__ int   d_segid[BB * SS];
__device__ int   d_nedges[BB];
__device__ float d_segsum[(size_t)BB * NSEG * VV];
__device__ int   d_segcnt[BB * NSEG];
__device__ float d_attnseg[(size_t)BB * NSEG * VV];
__device__ float d_A[VV * VV];
__device__ float d_WvT[VV * VV];
__device__ float d_w1[VV];
__device__ float d_qb[VV];
__device__ float d_bqbk;
__device__ float d_alpha[BB * VV];
__device__ float d_r[BB * VV];
__device__ float d_cextra[BB * VV];
__device__ float d_H[BB * VV * VV];
__device__ float d_M[BB * VV * VV];
__device__ float d_c[BB * VV];

// packed f32x2 helpers (Blackwell)
__device__ __forceinline__ void ffma2(float2& d, float2 a, float2 b) {
    asm("fma.rn.f32x2 %0, %1, %2, %0;"
        : "+l"(reinterpret_cast<unsigned long long&>(d))
        : "l"(reinterpret_cast<unsigned long long&>(a)),
          "l"(reinterpret_cast<unsigned long long&>(b)));
}
__device__ __forceinline__ unsigned long long add2(unsigned long long a, unsigned long long b) {
    unsigned long long d;
    asm("add.rn.f32x2 %0, %1, %2;" : "=l"(d) : "l"(a), "l"(b));
    return d;
}
union F4 { float4 v; unsigned long long u[2]; };

// vectorized global reduction
__device__ __forceinline__ void red4(float* p, float4 v) {
    asm volatile("red.global.add.v4.f32 [%0], {%1,%2,%3,%4};"
        :: "l"(p), "f"(v.x), "f"(v.y), "f"(v.z), "f"(v.w) : "memory");
}

// ---------------- 1) PE table ----------------
__global__ void k_pe() {
    int gid = blockIdx.x * blockDim.x + threadIdx.x;
    int t = gid >> 6, i = gid & 63;
    const float kScale = -0.07195578472185053f;
    float div = expf((float)(2 * i) * kScale);
    float s, c;
    sincosf((float)t * div, &s, &c);
    d_pe[t * VV + 2 * i]     = s;
    d_pe[t * VV + 2 * i + 1] = c;
}

// ---------------- 2) rising-edge scan ----------------
__global__ void k_scan(const float* __restrict__ sp, float* __restrict__ out, int tail) {
    int b = blockIdx.x, tid = threadIdx.x;
    int base = tid * 16;
    const float* row = sp + (size_t)b * SS;
    float prev = (base == 0) ? -1.0f : row[base - 1];
    int loc[16]; int run = 0;
#pragma unroll
    for (int e = 0; e < 16; e++) {
        float cur = row[base + e];
        int mk = (cur >= 0.5f) && !(prev >= 0.5f);
        run += mk; loc[e] = run; prev = cur;
    }
    __shared__ int ss[256];
    ss[tid] = run; __syncthreads();
    int val = run;
    for (int o = 1; o < 256; o <<= 1) {
        int add = (tid >= o) ? ss[tid - o] : 0;
        __syncthreads();
        val += add; ss[tid] = val;
        __syncthreads();
    }
    int excl = val - run;
#pragma unroll
    for (int e = 0; e < 16; e++) d_segid[b * SS + base + e] = excl + loc[e];
    if (tid == 255) {
        d_nedges[b] = val;
        if (b < tail) out[(size_t)OUTMAIN + b] = (float)(val + 1);
    }
    if (b == 0) {
        for (int idx = BB + tid; idx < tail; idx += 256) out[(size_t)OUTMAIN + idx] = 0.f;
    }
}

// ---------------- 3) bounded zero (after scan) ----------------
__global__ void k_zero() {
    int b = blockIdx.y;
    int nz = d_nedges[b] + 1;
    float4 z = make_float4(0.f, 0.f, 0.f, 0.f);
    int tid = blockIdx.x * 256 + threadIdx.x, stride = gridDim.x * 256;
    float4* G4 = (float4*)(d_G + (size_t)b * VV * VV);
    for (int i = tid; i < VV * VV / 4; i += stride) G4[i] = z;
    float4* S4 = (float4*)(d_segsum + (size_t)b * NSEG * VV);
    int ns4 = nz * (VV / 4);
    for (int i = tid; i < ns4; i += stride) S4[i] = z;
    int* C = d_segcnt + b * NSEG;
    for (int i = tid; i < nz; i += stride) C[i] = 0;
}

// ---------------- 4) precompute A, WvT, w1, qb, bqbk (parallelized) ----------------
__global__ void k_p0(const float* __restrict__ Wq, const float* __restrict__ bq,
                     const float* __restrict__ Wk, const float* __restrict__ bk,
                     const float* __restrict__ Wv) {
    int a = blockIdx.x, tid = threadIdx.x;
    __shared__ float wq[VV], red1[VV], red2[VV];
    wq[tid] = Wq[tid * VV + a];
    float wkca = Wk[tid * VV + a];
    __syncthreads();
    float acc = 0.f;
    for (int i = 0; i < VV; i++) acc += wq[i] * Wk[i * VV + tid];
    d_A[a * VV + tid] = acc * (1.f / 64.f);
    d_WvT[a * VV + tid] = Wv[tid * VV + a];
    red1[tid] = wq[tid] * bk[tid];
    red2[tid] = bq[tid] * wkca;
    __syncthreads();
    for (int o = 64; o > 0; o >>= 1) {
        if (tid < o) { red1[tid] += red1[tid + o]; red2[tid] += red2[tid + o]; }
        __syncthreads();
    }
    if (tid == 0) { d_qb[a] = red1[0]; d_w1[a] = red2[0] * (1.f / 64.f); }
    if (a == 0) {
        __syncthreads();
        red1[tid] = bq[tid] * bk[tid];
        __syncthreads();
        for (int o = 64; o > 0; o >>= 1) {
            if (tid < o) red1[tid] += red1[tid + o];
            __syncthreads();
        }
        if (tid == 0) d_bqbk = red1[0];
    }
}

// ---------------- 5) main: x1 + Gram(upper) + segment sums (all float4) ----------------
__global__ void __launch_bounds__(256, 2)
k_main(const float* __restrict__ bert, float* __restrict__ out) {
    extern __shared__ float sm[];
    float* xs = sm;
    int*  sgid = (int*)(sm + TS * VV);
    int b = blockIdx.y, t0 = blockIdx.x * TS, tid = threadIdx.x;

    const float4* bp4 = (const float4*)(bert + ((size_t)b * SS + t0) * VV);
    const float4* pe4 = (const float4*)d_pe + (size_t)t0 * 32;
    float4* out4 = (float4*)(out + ((size_t)b * SS + t0) * (2 * VV));
    float4* xs4 = (float4*)xs;

#pragma unroll
    for (int k = 0; k < 16; k++) {
        int idx = tid + k * 256;
        int t = idx >> 5, v4 = idx & 31;
        F4 x, p, x1, xq;
        x.v = bp4[idx];
        p.v = pe4[idx];
        x1.u[0] = add2(x.u[0], p.u[0]);
        x1.u[1] = add2(x.u[1], p.u[1]);
        xq.u[0] = add2(x1.u[0], p.u[0]);
        xq.u[1] = add2(x1.u[1], p.u[1]);
        out4[t * 64 + 32 + v4] = x1.v;      // x1 half of output
        xs4[idx] = xq.v;                    // xseq
    }
    for (int i = tid; i < TS; i += 256) sgid[i] = d_segid[b * SS + t0 + i];
    __syncthreads();

    // Gram: 136 upper-triangle 8x8 tiles
    if (tid < 136) {
        int rem = tid, ti = 0;
        while (rem >= 16 - ti) { rem -= 16 - ti; ti++; }
        int tj = ti + rem;
        int a0 = ti * 8, c0 = tj * 8;
        float2 acc2[8][4];
#pragma unroll
        for (int p = 0; p < 8; p++)
#pragma unroll
            for (int q = 0; q < 4; q++) acc2[p][q] = make_float2(0.f, 0.f);

        for (int t = 0; t < TS; t++) {
            const float4 A0 = *(const float4*)&xs[t * VV + a0];
            const float4 A1 = *(const float4*)&xs[t * VV + a0 + 4];
            const float4 C0 = *(const float4*)&xs[t * VV + c0];
            const float4 C1 = *(const float4*)&xs[t * VV + c0 + 4];
            float av[8] = {A0.x, A0.y, A0.z, A0.w, A1.x, A1.y, A1.z, A1.w};
            float2 cp[4] = {make_float2(C0.x, C0.y), make_float2(C0.z, C0.w),
                            make_float2(C1.x, C1.y), make_float2(C1.z, C1.w)};
#pragma unroll
            for (int p = 0; p < 8; p++) {
                float2 ap = make_float2(av[p], av[p]);
#pragma unroll
                for (int q = 0; q < 4; q++) ffma2(acc2[p][q], ap, cp[q]);
            }
        }
        float* Gb = d_G + (size_t)b * VV * VV;
#pragma unroll
        for (int p = 0; p < 8; p++) {
            red4(&Gb[(a0 + p) * VV + c0],
                 make_float4(acc2[p][0].x, acc2[p][0].y, acc2[p][1].x, acc2[p][1].y));
            red4(&Gb[(a0 + p) * VV + c0 + 4],
                 make_float4(acc2[p][2].x, acc2[p][2].y, acc2[p][3].x, acc2[p][3].y));
        }
    }

    // segment sums: 8 token-chunks x 32 v4-groups (vectorized, red.v4 flush)
    {
        int half = tid >> 5, v4 = tid & 31;
        int ts = half * 16, te = ts + 16;
        float4 acc = make_float4(0.f, 0.f, 0.f, 0.f);
        int cur = sgid[ts], cnt = 0;
        for (int t = ts; t < te; t++) {
            int s = sgid[t];
            if (s != cur) {
                red4(&d_segsum[((size_t)b * NSEG + cur) * VV + v4 * 4], acc);
                if (v4 == 0) atomicAdd(&d_segcnt[b * NSEG + cur], cnt);
                acc = make_float4(0.f, 0.f, 0.f, 0.f); cnt = 0; cur = s;
            }
            float4 x = xs4[t * 32 + v4];
            acc.x += x.x; acc.y += x.y; acc.z += x.z; acc.w += x.w;
            cnt++;
        }
        red4(&d_segsum[((size_t)b * NSEG + cur) * VV + v4 * 4], acc);
        if (v4 == 0) atomicAdd(&d_segcnt[b * NSEG + cur], cnt);
    }
}

// ---------------- 6) per-batch small vectors (sx from segsum) ----------------
__global__ void k_vec(const float* __restrict__ Wq, const float* __restrict__ bq,
                      const float* __restrict__ Wk, const float* __restrict__ Wv,
                      const float* __restrict__ bv) {
    int b = blockIdx.x, tid = threadIdx.x;
    __shared__ float sxs[VV], ps[VV], rs[VV], red[VV];
    int ne = d_nedges[b];
    float s = 0.f;
    for (int g = 0; g <= ne; g++) s += d_segsum[((size_t)b * NSEG + g) * VV + tid];
    sxs[tid] = s;
    __syncthreads();
    float p = 0.f, r = 0.f;
    for (int e = 0; e < VV; e++) {
        p += Wk[tid * VV + e] * sxs[e];
        r += Wv[tid * VV + e] * sxs[e];
    }
    ps[tid] = p; rs[tid] = r;
    d_r[b * VV + tid] = r;
    __syncthreads();
    float qp = 0.f;
    for (int i = 0; i < VV; i++) qp += Wq[i * VV + tid] * ps[i];
    d_alpha[b * VV + tid] = (qp + (float)SS * d_qb[tid]) * (1.f / 64.f);
    red[tid] = bq[tid] * ps[tid];
    __syncthreads();
    for (int o = 64; o > 0; o >>= 1) {
        if (tid < o) red[tid] += red[tid + o];
        __syncthreads();
    }
    float bqp = red[0];
    d_cextra[b * VV + tid] =
        (bqp * bv[tid] + d_bqbk * (rs[tid] + (float)SS * bv[tid])) * (1.f / 64.f);
}

// ---------------- 7) H = G @ Wv^T (symmetric read of upper G) ----------------
__global__ void k_h() {
    int b = blockIdx.y, e0 = blockIdx.x * 16, tid = threadIdx.x;
    __shared__ float Gs[16 * VV];
    const float* Gb = d_G + (size_t)b * VV * VV;
#pragma unroll
    for (int r = 0; r < 16; r++) {
        int e = e0 + r;
        int mn = min(e, tid), mx = max(e, tid);
        Gs[r * VV + tid] = Gb[mn * VV + mx];
    }
    __syncthreads();
    float acc[16];
#pragma unroll
    for (int e = 0; e < 16; e++) acc[e] = 0.f;
    for (int c = 0; c < VV; c++) {
        float w = d_WvT[c * VV + tid];
#pragma unroll
        for (int e = 0; e < 16; e++) acc[e] += Gs[e * VV + c] * w;
    }
    float* Hb = d_H + (size_t)b * VV * VV;
#pragma unroll
    for (int e = 0; e < 16; e++) Hb[(e0 + e) * VV + tid] = acc[e];
}

// ---------------- 8) M = A @ H + rank1, c = w1 @ H + cextra ----------------
__global__ void k_m(const float* __restrict__ bv) {
    int b = blockIdx.y, rg = blockIdx.x, a0 = rg * 16, tid = threadIdx.x;
    __shared__ float As[16 * VV], w1s[VV];
#pragma unroll
    for (int r = 0; r < 16; r++) As[r * VV + tid] = d_A[(a0 + r) * VV + tid];
    w1s[tid] = d_w1[tid];
    __syncthreads();
    float acc[16]; float cacc = 0.f;
#pragma unroll
    for (int a = 0; a < 16; a++) acc[a] = 0.f;
    const float* Hb = d_H + (size_t)b * VV * VV;
    for (int e = 0; e < VV; e++) {
        float h = Hb[e * VV + tid];
#pragma unroll
        for (int a = 0; a < 16; a++) acc[a] += As[a * VV + e] * h;
        if (rg == 0) cacc += w1s[e] * h;
    }
    float bvj = bv[tid];
    float rj  = d_r[b * VV + tid];
    float* Mb = d_M + (size_t)b * VV * VV;
#pragma unroll
    for (int a = 0; a < 16; a++)
        Mb[(a0 + a) * VV + tid] = acc[a] + d_alpha[b * VV + a0 + a] * bvj
                                + (d_qb[a0 + a] * (1.f / 64.f)) * rj;
    if (rg == 0) d_c[b * VV + tid] = cacc + d_cextra[b * VV + tid];
}

// ---------------- 9) attnseg = mean @ M + c ----------------
__global__ void k_attnseg() {
    int b = blockIdx.y, g0 = blockIdx.x * 16, tid = threadIdx.x;
    int ne = d_nedges[b];
    if (g0 > ne) return;
    int ng = min(16, ne + 1 - g0);
    __shared__ float mean[16 * VV];
#pragma unroll
    for (int r = 0; r < 16; r++) {
        float val = 0.f;
        if (r < ng) {
            int cnt = d_segcnt[b * NSEG + g0 + r];
            float den = fmaxf((float)cnt, 1.f);
            val = d_segsum[((size_t)b * NSEG + g0 + r) * VV + tid] / den;
        }
        mean[r * VV + tid] = val;
    }
    __syncthreads();
    float cj = d_c[b * VV + tid];
    float acc[16];
#pragma unroll
    for (int s = 0; s < 16; s++) acc[s] = cj;
    const float* Mb = d_M + (size_t)b * VV * VV;
    for (int v = 0; v < VV; v++) {
        float m = Mb[v * VV + tid];
#pragma unroll
        for (int s = 0; s < 16; s++) acc[s] += mean[s * VV + v] * m;
    }
    for (int s = 0; s < ng; s++)
        d_attnseg[((size_t)b * NSEG + g0 + s) * VV + tid] = acc[s];
}

// ---------------- 10) broadcast to tokens (float4) ----------------
__global__ void k_out(float* __restrict__ out) {
    int b = blockIdx.y, t0 = blockIdx.x * 64, tid = threadIdx.x;
    __shared__ int sg[64];
    if (tid < 64) sg[tid] = d_segid[b * SS + t0 + tid];
    __syncthreads();
    const float4* as4 = (const float4*)d_attnseg;
    float4* o4 = (float4*)(out + ((size_t)b * SS + t0) * (2 * VV));
#pragma unroll
    for (int k = 0; k < 8; k++) {
        int idx = tid + k * 256;
        int t = idx >> 5, v4 = idx & 31;
        o4[t * 64 + v4] = as4[((size_t)b * NSEG + sg[t]) * 32 + v4];
    }
}

// ---------------- launch ----------------
extern "C" void kernel_launch(void* const* d_in, const int* in_sizes, int n_in,
                              void* d_out, int out_size) {
    const float* bert = (const float*)d_in[0];
    const float* sp   = (const float*)d_in[1];
    const float* Wq   = (const float*)d_in[2];
    const float* bq   = (const float*)d_in[3];
    const float* Wk   = (const float*)d_in[4];
    const float* bk   = (const float*)d_in[5];
    const float* Wv   = (const float*)d_in[6];
    const float* bv   = (const float*)d_in[7];
    float* out = (float*)d_out;
    int tail = out_size - OUTMAIN;
    if (tail < 0) tail = 0;

    const int smem_main = TS * VV * sizeof(float) + TS * sizeof(int);
    cudaFuncSetAttribute(k_main, cudaFuncAttributeMaxDynamicSharedMemorySize, smem_main);

    k_pe<<<(SS * 64) / 128, 128>>>();
    k_scan<<<BB, 256>>>(sp, out, tail);
    k_zero<<<dim3(32, BB), 256>>>();
    k_p0<<<VV, VV>>>(Wq, bq, Wk, bk, Wv);
    k_main<<<dim3(SS / TS, BB), 256, smem_main>>>(bert, out);
    k_vec<<<BB, VV>>>(Wq, bq, Wk, Wv, bv);
    k_h<<<dim3(8, BB), VV>>>();
    k_m<<<dim3(8, BB), VV>>>(bv);
    k_attnseg<<<dim3((NSEG + 15) / 16, BB), VV>>>();
    k_out<<<dim3(SS / 64, BB), 256>>>(out);
}

// round 3
// speedup vs baseline: 1.4876x; 1.1490x over previous
#include <cuda_runtime.h>
#include <cuda_bf16.h>
#include <cstdint>

#define BB   32
#define SS   4096
#define VV   128
#define NSEG 2050
#define OUTMAIN (BB * SS * 2 * VV)
#define TS   128

// ---------------- device scratch ----------------
__device__ float d_pe[SS * VV];
__device__ float d_G[BB * VV * VV];
__device__ float d_sx[BB * VV];
__device__ int   d_segid[BB * SS];
__device__ int   d_nedges[BB];
__device__ float d_segsum[(size_t)BB * NSEG * VV];
__device__ int   d_segcnt[BB * NSEG];
__device__ float d_attnseg[(size_t)BB * NSEG * VV];
__device__ float d_A[VV * VV];
__device__ float d_w1[VV];
__device__ float d_qb[VV];
__device__ float d_bqbk;
__device__ float d_M[BB * VV * VV];
__device__ float d_c[BB * VV];

// packed f32x2 helpers
__device__ __forceinline__ void ffma2(float2& d, float2 a, float2 b) {
    asm("fma.rn.f32x2 %0, %1, %2, %0;"
        : "+l"(reinterpret_cast<unsigned long long&>(d))
        : "l"(reinterpret_cast<unsigned long long&>(a)),
          "l"(reinterpret_cast<unsigned long long&>(b)));
}
__device__ __forceinline__ unsigned long long add2(unsigned long long a, unsigned long long b) {
    unsigned long long d;
    asm("add.rn.f32x2 %0, %1, %2;" : "=l"(d) : "l"(a), "l"(b));
    return d;
}
union F4 { float4 v; unsigned long long u[2]; };

__device__ __forceinline__ void red4(float* p, float4 v) {
    asm volatile("red.global.add.v4.f32 [%0], {%1,%2,%3,%4};"
        :: "l"(p), "f"(v.x), "f"(v.y), "f"(v.z), "f"(v.w) : "memory");
}

// ================= 1) prep: pe + scan + p0 + zero(G,sx) =================
#define PE_BLKS   1024
#define SCAN_BLKS 32
#define P0_BLKS   16
#define ZERO_BLKS 32
#define PREP_GRID (PE_BLKS + SCAN_BLKS + P0_BLKS + ZERO_BLKS)

__global__ void k_prep(const float* __restrict__ sp,
                       const float* __restrict__ Wq, const float* __restrict__ bq,
                       const float* __restrict__ Wk, const float* __restrict__ bk,
                       float* __restrict__ out, int tail) {
    int bx = blockIdx.x, tid = threadIdx.x;

    if (bx < PE_BLKS) {                      // ---- PE table ----
        int gid = bx * 256 + tid;
        int t = gid >> 6, i = gid & 63;
        const float kScale = -0.07195578472185053f;
        float div = expf((float)(2 * i) * kScale);
        float s, c;
        sincosf((float)t * div, &s, &c);
        d_pe[t * VV + 2 * i]     = s;
        d_pe[t * VV + 2 * i + 1] = c;
        return;
    }
    if (bx < PE_BLKS + SCAN_BLKS) {          // ---- rising-edge scan ----
        int b = bx - PE_BLKS;
        int base = tid * 16;
        const float* row = sp + (size_t)b * SS;
        float prev = (base == 0) ? -1.0f : row[base - 1];
        int loc[16]; int run = 0;
#pragma unroll
        for (int e = 0; e < 16; e++) {
            float cur = row[base + e];
            int mk = (cur >= 0.5f) && !(prev >= 0.5f);
            run += mk; loc[e] = run; prev = cur;
        }
        __shared__ int ss[256];
        ss[tid] = run; __syncthreads();
        int val = run;
        for (int o = 1; o < 256; o <<= 1) {
            int add = (tid >= o) ? ss[tid - o] : 0;
            __syncthreads();
            val += add; ss[tid] = val;
            __syncthreads();
        }
        int excl = val - run;
#pragma unroll
        for (int e = 0; e < 16; e++) d_segid[b * SS + base + e] = excl + loc[e];
        if (tid == 255) {
            d_nedges[b] = val;
            if (b < tail) out[(size_t)OUTMAIN + b] = (float)(val + 1);
        }
        if (b == 0) {
            for (int idx = BB + tid; idx < tail; idx += 256) out[(size_t)OUTMAIN + idx] = 0.f;
        }
        return;
    }
    if (bx < PE_BLKS + SCAN_BLKS + P0_BLKS) { // ---- A, qb, w1, bqbk ----
        int p = bx - PE_BLKS - SCAN_BLKS;
        int a0 = p * 8;
        __shared__ float Wqs[1024];          // [i*8 + ar]
        for (int idx = tid; idx < 1024; idx += 256) {
            int i = idx >> 3, ar = idx & 7;
            Wqs[idx] = Wq[i * VV + a0 + ar];
        }
        __syncthreads();
        int col = tid & 127, half = tid >> 7;
        float acc[4] = {0.f, 0.f, 0.f, 0.f};
#pragma unroll 4
        for (int i = 0; i < 128; i++) {
            float wk = Wk[i * VV + col];
#pragma unroll
            for (int h = 0; h < 4; h++) acc[h] += Wqs[i * 8 + half * 4 + h] * wk;
        }
#pragma unroll
        for (int h = 0; h < 4; h++)
            d_A[(a0 + half * 4 + h) * VV + col] = acc[h] * (1.f / 64.f);

        int ar = tid >> 5, lane = tid & 31;
        int a = a0 + ar;
        float q1 = 0.f, q2 = 0.f;
        for (int i = lane; i < 128; i += 32) {
            q1 += Wqs[i * 8 + ar] * bk[i];
            q2 += bq[i] * Wk[i * VV + a];
        }
#pragma unroll
        for (int o = 16; o > 0; o >>= 1) {
            q1 += __shfl_down_sync(0xffffffff, q1, o);
            q2 += __shfl_down_sync(0xffffffff, q2, o);
        }
        if (lane == 0) { d_qb[a] = q1; d_w1[a] = q2 * (1.f / 64.f); }
        if (p == 0 && tid < 32) {
            float z = 0.f;
            for (int i = tid; i < 128; i += 32) z += bq[i] * bk[i];
#pragma unroll
            for (int o = 16; o > 0; o >>= 1) z += __shfl_down_sync(0xffffffff, z, o);
            if (tid == 0) d_bqbk = z;
        }
        return;
    }
    { // ---- zero G + sx ----
        int zb = bx - PE_BLKS - SCAN_BLKS - P0_BLKS;
        float4 z = make_float4(0.f, 0.f, 0.f, 0.f);
        int i0 = zb * 256 + tid, stride = ZERO_BLKS * 256;
        float4* G4 = (float4*)d_G;
        for (int i = i0; i < BB * VV * VV / 4; i += stride) G4[i] = z;
        float4* S4 = (float4*)d_sx;
        for (int i = i0; i < BB * VV / 4; i += stride) S4[i] = z;
    }
}

// ================= 2) bounded zero of segsum/segcnt =================
__global__ void k_zseg() {
    int b = blockIdx.y;
    int nz = d_nedges[b] + 1;
    float4 z = make_float4(0.f, 0.f, 0.f, 0.f);
    int i0 = blockIdx.x * 256 + threadIdx.x, stride = gridDim.x * 256;
    float4* S4 = (float4*)(d_segsum + (size_t)b * NSEG * VV);
    int ns4 = nz * (VV / 4);
    for (int i = i0; i < ns4; i += stride) S4[i] = z;
    int* C = d_segcnt + b * NSEG;
    for (int i = i0; i < nz; i += stride) C[i] = 0;
}

// ================= 3) main: x1 + Gram(upper) + segment sums + sx =================
__global__ void __launch_bounds__(256, 2)
k_main(const float* __restrict__ bert, float* __restrict__ out) {
    extern __shared__ float sm[];
    float* xs = sm;
    int*  sgid = (int*)(sm + TS * VV);
    int b = blockIdx.y, t0 = blockIdx.x * TS, tid = threadIdx.x;

    const float4* bp4 = (const float4*)(bert + ((size_t)b * SS + t0) * VV);
    const float4* pe4 = (const float4*)d_pe + (size_t)t0 * 32;
    float4* out4 = (float4*)(out + ((size_t)b * SS + t0) * (2 * VV));
    float4* xs4 = (float4*)xs;

#pragma unroll
    for (int k = 0; k < 16; k++) {
        int idx = tid + k * 256;
        int t = idx >> 5, v4 = idx & 31;
        F4 x, p, x1, xq;
        x.v = bp4[idx];
        p.v = pe4[idx];
        x1.u[0] = add2(x.u[0], p.u[0]);
        x1.u[1] = add2(x.u[1], p.u[1]);
        xq.u[0] = add2(x1.u[0], p.u[0]);
        xq.u[1] = add2(x1.u[1], p.u[1]);
        out4[t * 64 + 32 + v4] = x1.v;
        xs4[idx] = xq.v;
    }
    for (int i = tid; i < TS; i += 256) sgid[i] = d_segid[b * SS + t0 + i];
    __syncthreads();

    if (tid < 136) {
        int rem = tid, ti = 0;
        while (rem >= 16 - ti) { rem -= 16 - ti; ti++; }
        int tj = ti + rem;
        int a0 = ti * 8, c0 = tj * 8;
        float2 acc2[8][4];
#pragma unroll
        for (int p = 0; p < 8; p++)
#pragma unroll
            for (int q = 0; q < 4; q++) acc2[p][q] = make_float2(0.f, 0.f);

        for (int t = 0; t < TS; t++) {
            const float4 A0 = *(const float4*)&xs[t * VV + a0];
            const float4 A1 = *(const float4*)&xs[t * VV + a0 + 4];
            const float4 C0 = *(const float4*)&xs[t * VV + c0];
            const float4 C1 = *(const float4*)&xs[t * VV + c0 + 4];
            float av[8] = {A0.x, A0.y, A0.z, A0.w, A1.x, A1.y, A1.z, A1.w};
            float2 cp[4] = {make_float2(C0.x, C0.y), make_float2(C0.z, C0.w),
                            make_float2(C1.x, C1.y), make_float2(C1.z, C1.w)};
#pragma unroll
            for (int p = 0; p < 8; p++) {
                float2 ap = make_float2(av[p], av[p]);
#pragma unroll
                for (int q = 0; q < 4; q++) ffma2(acc2[p][q], ap, cp[q]);
            }
        }
        float* Gb = d_G + (size_t)b * VV * VV;
#pragma unroll
        for (int p = 0; p < 8; p++) {
            red4(&Gb[(a0 + p) * VV + c0],
                 make_float4(acc2[p][0].x, acc2[p][0].y, acc2[p][1].x, acc2[p][1].y));
            red4(&Gb[(a0 + p) * VV + c0 + 4],
                 make_float4(acc2[p][2].x, acc2[p][2].y, acc2[p][3].x, acc2[p][3].y));
        }
    }

    {   // segment sums + sx
        int half = tid >> 5, v4 = tid & 31;
        int ts = half * 16, te = ts + 16;
        float4 acc = make_float4(0.f, 0.f, 0.f, 0.f);
        float4 tot = make_float4(0.f, 0.f, 0.f, 0.f);
        int cur = sgid[ts], cnt = 0;
        for (int t = ts; t < te; t++) {
            int s = sgid[t];
            if (s != cur) {
                red4(&d_segsum[((size_t)b * NSEG + cur) * VV + v4 * 4], acc);
                if (v4 == 0) atomicAdd(&d_segcnt[b * NSEG + cur], cnt);
                acc = make_float4(0.f, 0.f, 0.f, 0.f); cnt = 0; cur = s;
            }
            float4 x = xs4[t * 32 + v4];
            acc.x += x.x; acc.y += x.y; acc.z += x.z; acc.w += x.w;
            tot.x += x.x; tot.y += x.y; tot.z += x.z; tot.w += x.w;
            cnt++;
        }
        red4(&d_segsum[((size_t)b * NSEG + cur) * VV + v4 * 4], acc);
        if (v4 == 0) atomicAdd(&d_segcnt[b * NSEG + cur], cnt);
        red4(&d_sx[b * VV + v4 * 4], tot);
    }
}

// ================= 4) fused chain: vectors + H + M + c =================
// grid (4, BB), 256 threads; block cb handles columns j0=cb*32 .. +31
__global__ void __launch_bounds__(256, 2)
k_chain(const float* __restrict__ Wq, const float* __restrict__ bq,
        const float* __restrict__ Wk, const float* __restrict__ Wv,
        const float* __restrict__ bv) {
    extern __shared__ float sm[];
    float* Gs  = sm;              // 16384 (reused as As)
    float* Wvs = Gs + 16384;      // 128*33
    float* Hs  = Wvs + 4224;      // 128*33
    float* sxs = Hs + 4224;       // 128
    float* ps  = sxs + 128;       // 128
    float* alph= ps + 128;        // 128
    float* rr  = alph + 128;      // 32
    float* cex = rr + 32;         // 32
    float* redb= cex + 32;        // 32

    int b = blockIdx.y, cb = blockIdx.x, j0 = cb * 32, tid = threadIdx.x;
    const float* Gb = d_G + (size_t)b * VV * VV;

    if (tid < 128) sxs[tid] = d_sx[b * VV + tid];
    // G symmetric -> smem
    for (int idx = tid; idx < VV * VV; idx += 256) {
        int e = idx >> 7, c = idx & 127;
        int mn = min(e, c), mx = e + c - mn;
        Gs[idx] = Gb[mn * VV + mx];
    }
    // Wv columns for this block: Wvs[c*33 + r] = Wv[(j0+r)*128 + c]
    for (int idx = tid; idx < 32 * VV; idx += 256) {
        int r = idx >> 7, c = idx & 127;
        Wvs[c * 33 + r] = Wv[(j0 + r) * VV + c];
    }
    __syncthreads();

    // p = Wk @ sx ; r = Wv(rows j0..) @ sx
    if (tid < 128) {
        const float4* wkr = (const float4*)(Wk + (size_t)tid * VV);
        const float4* sx4 = (const float4*)sxs;
        float a = 0.f;
#pragma unroll 8
        for (int i = 0; i < 32; i++) {
            float4 w = wkr[i], s = sx4[i];
            a += w.x * s.x + w.y * s.y + w.z * s.z + w.w * s.w;
        }
        ps[tid] = a;
    } else if (tid < 160) {
        int jj = tid - 128;
        const float4* wvr = (const float4*)(Wv + (size_t)(j0 + jj) * VV);
        const float4* sx4 = (const float4*)sxs;
        float a = 0.f;
#pragma unroll 8
        for (int i = 0; i < 32; i++) {
            float4 w = wvr[i], s = sx4[i];
            a += w.x * s.x + w.y * s.y + w.z * s.z + w.w * s.w;
        }
        rr[jj] = a;
    }
    __syncthreads();

    // alpha = (Wq^T p + S*qb)/64 ; bqp = bq.p
    if (tid < 128) {
        float qp = 0.f;
#pragma unroll 4
        for (int i = 0; i < 128; i++) qp += Wq[i * VV + tid] * ps[i];
        alph[tid] = (qp + (float)SS * d_qb[tid]) * (1.f / 64.f);
    } else if (tid < 160) {
        int lane = tid - 128;
        float z = 0.f;
        for (int i = lane; i < 128; i += 32) z += bq[i] * ps[i];
#pragma unroll
        for (int o = 16; o > 0; o >>= 1) z += __shfl_down_sync(0xffffffff, z, o);
        if (lane == 0) redb[0] = z;
    }

    // H = G @ Wv^T (columns j0..j0+31)
    int w = tid >> 5, jj = tid & 31;
    {
        float hacc[16];
#pragma unroll
        for (int e = 0; e < 16; e++) hacc[e] = 0.f;
        for (int c = 0; c < 128; c += 4) {
            float wv0 = Wvs[c * 33 + jj];
            float wv1 = Wvs[(c + 1) * 33 + jj];
            float wv2 = Wvs[(c + 2) * 33 + jj];
            float wv3 = Wvs[(c + 3) * 33 + jj];
#pragma unroll
            for (int e = 0; e < 16; e++) {
                const float4 g = *(const float4*)(Gs + (w * 16 + e) * VV + c);
                hacc[e] += g.x * wv0 + g.y * wv1 + g.z * wv2 + g.w * wv3;
            }
        }
#pragma unroll
        for (int e = 0; e < 16; e++) Hs[(w * 16 + e) * 33 + jj] = hacc[e];
    }
    __syncthreads();

    // cextra (needs bqp, rr)
    if (tid < 32)
        cex[tid] = (redb[0] * bv[j0 + tid] + d_bqbk * (rr[tid] + (float)SS * bv[j0 + tid])) * (1.f / 64.f);

    // load A into Gs (reuse)
    {
        float4* G4 = (float4*)Gs;
        const float4* A4 = (const float4*)d_A;
        for (int idx = tid; idx < VV * VV / 4; idx += 256) G4[idx] = A4[idx];
    }
    __syncthreads();

    // M = A @ H + alpha*bv^T + (qb/64)*r^T
    {
        float macc[16];
#pragma unroll
        for (int a = 0; a < 16; a++) macc[a] = 0.f;
        for (int e = 0; e < 128; e += 4) {
            float h0 = Hs[e * 33 + jj];
            float h1 = Hs[(e + 1) * 33 + jj];
            float h2 = Hs[(e + 2) * 33 + jj];
            float h3 = Hs[(e + 3) * 33 + jj];
#pragma unroll
            for (int a = 0; a < 16; a++) {
                const float4 av = *(const float4*)(Gs + (w * 16 + a) * VV + e);
                macc[a] += av.x * h0 + av.y * h1 + av.z * h2 + av.w * h3;
            }
        }
        float bvj = bv[j0 + jj];
        float rj  = rr[jj];
        float* Mb = d_M + (size_t)b * VV * VV;
#pragma unroll
        for (int a = 0; a < 16; a++) {
            int arow = w * 16 + a;
            Mb[arow * VV + j0 + jj] = macc[a] + alph[arow] * bvj
                                    + d_qb[arow] * (1.f / 64.f) * rj;
        }
    }

    // c = w1 @ H + cextra
    if (tid < 32) {
        float cacc = 0.f;
#pragma unroll 4
        for (int e = 0; e < 128; e++) cacc += d_w1[e] * Hs[e * 33 + tid];
        d_c[b * VV + j0 + tid] = cacc + cex[tid];
    }
}

// ================= 5) attnseg = mean @ M + c (M in smem, 32 segs/block) =================
__global__ void __launch_bounds__(256, 2)
k_attnseg() {
    extern __shared__ float sm[];
    float* Ms   = sm;            // 16384
    float* mean = Ms + 16384;    // 32*128
    int b = blockIdx.y, g0 = blockIdx.x * 32, tid = threadIdx.x;
    int ne = d_nedges[b];
    if (g0 > ne) return;
    int ng = min(32, ne + 1 - g0);

    {
        float4* M4 = (float4*)Ms;
        const float4* S4 = (const float4*)(d_M + (size_t)b * VV * VV);
        for (int idx = tid; idx < VV * VV / 4; idx += 256) M4[idx] = S4[idx];
    }
    for (int idx = tid; idx < 32 * VV; idx += 256) {
        int s = idx >> 7, v = idx & 127;
        float val = 0.f;
        if (s < ng) {
            float den = fmaxf((float)d_segcnt[b * NSEG + g0 + s], 1.f);
            val = d_segsum[((size_t)b * NSEG + g0 + s) * VV + v] / den;
        }
        mean[idx] = val;
    }
    __syncthreads();

    int sh = tid >> 7, j = tid & 127;
    float cj = d_c[b * VV + j];
    float acc[16];
#pragma unroll
    for (int s = 0; s < 16; s++) acc[s] = cj;
    for (int v = 0; v < 128; v += 4) {
        float m0 = Ms[v * VV + j];
        float m1 = Ms[(v + 1) * VV + j];
        float m2 = Ms[(v + 2) * VV + j];
        float m3 = Ms[(v + 3) * VV + j];
#pragma unroll
        for (int s = 0; s < 16; s++) {
            const float4 mn = *(const float4*)(mean + (sh * 16 + s) * VV + v);
            acc[s] += mn.x * m0 + mn.y * m1 + mn.z * m2 + mn.w * m3;
        }
    }
#pragma unroll
    for (int s = 0; s < 16; s++) {
        int g = sh * 16 + s;
        if (g < ng)
            d_attnseg[((size_t)b * NSEG + g0 + g) * VV + j] = acc[s];
    }
}

// ================= 6) broadcast to tokens =================
__global__ void k_out(float* __restrict__ out) {
    int b = blockIdx.y, t0 = blockIdx.x * 128, tid = threadIdx.x;
    __shared__ int sg[128];
    if (tid < 128) sg[tid] = d_segid[b * SS + t0 + tid];
    __syncthreads();
    const float4* as4 = (const float4*)d_attnseg;
    float4* o4 = (float4*)(out + ((size_t)b * SS + t0) * (2 * VV));
#pragma unroll
    for (int k = 0; k < 16; k++) {
        int idx = tid + k * 256;
        int t = idx >> 5, v4 = idx & 31;
        o4[t * 64 + v4] = as4[((size_t)b * NSEG + sg[t]) * 32 + v4];
    }
}

// ================= launch =================
extern "C" void kernel_launch(void* const* d_in, const int* in_sizes, int n_in,
                              void* d_out, int out_size) {
    const float* bert = (const float*)d_in[0];
    const float* sp   = (const float*)d_in[1];
    const float* Wq   = (const float*)d_in[2];
    const float* bq   = (const float*)d_in[3];
    const float* Wk   = (const float*)d_in[4];
    const float* bk   = (const float*)d_in[5];
    const float* Wv   = (const float*)d_in[6];
    const float* bv   = (const float*)d_in[7];
    float* out = (float*)d_out;
    int tail = out_size - OUTMAIN;
    if (tail < 0) tail = 0;

    const int smem_main  = TS * VV * sizeof(float) + TS * sizeof(int);
    const int smem_chain = (16384 + 4224 + 4224 + 128 * 3 + 32 * 3) * sizeof(float);
    const int smem_att   = (16384 + 32 * VV) * sizeof(float);
    cudaFuncSetAttribute(k_main,    cudaFuncAttributeMaxDynamicSharedMemorySize, smem_main);
    cudaFuncSetAttribute(k_chain,   cudaFuncAttributeMaxDynamicSharedMemorySize, smem_chain);
    cudaFuncSetAttribute(k_attnseg, cudaFuncAttributeMaxDynamicSharedMemorySize, smem_att);

    k_prep<<<PREP_GRID, 256>>>(sp, Wq, bq, Wk, bk, out, tail);
    k_zseg<<<dim3(32, BB), 256>>>();
    k_main<<<dim3(SS / TS, BB), 256, smem_main>>>(bert, out);
    k_chain<<<dim3(4, BB), 256, smem_chain>>>(Wq, bq, Wk, Wv, bv);
    k_attnseg<<<dim3((NSEG + 31) / 32, BB), 256, smem_att>>>();
    k_out<<<dim3(SS / 128, BB), 256>>>(out);
}